// round 3
// baseline (speedup 1.0000x reference)
#include <cuda_runtime.h>
#include <math.h>

#define NB 8192      // batch (tokens)
#define NF 2048      // feature dim
#define NH 8192      // hidden dim
#define NO 2048      // out dim
#define NE 8         // experts
#define NSLOTS (NB * 2)

// -------------------- scratch (static device globals; no allocation) --------
__device__ int   g_counts[NE];
__device__ int   g_offsets[NE];
__device__ int   g_cursor[NE];
__device__ int   g_topi[NB * 2];
__device__ float g_topw[NB * 2];
__device__ int   g_rows[NSLOTS];     // slot -> token row
__device__ int   g_slotof[NB * 2];   // (token, j) -> slot
__device__ float g_H[(size_t)NSLOTS * NH];   // 512 MB hidden activations
__device__ float g_Y[(size_t)NSLOTS * NO];   // 128 MB expert outputs

// -------------------- small control kernels ---------------------------------
__global__ void init_kernel() {
    int i = threadIdx.x;
    if (i < NE) g_counts[i] = 0;
}

__global__ void prefix_kernel() {
    int off = 0;
    for (int e = 0; e < NE; e++) {
        g_offsets[e] = off;
        g_cursor[e]  = off;
        off += g_counts[e];
    }
}

// -------------------- router: one warp per token -----------------------------
__global__ void router_kernel(const float* __restrict__ feat,
                              const float* __restrict__ gW,
                              const float* __restrict__ gb,
                              const float* __restrict__ eb) {
    int warp = threadIdx.x >> 5;
    int lane = threadIdx.x & 31;
    int t = blockIdx.x * 8 + warp;
    if (t >= NB) return;

    const float* fr = feat + (size_t)t * NF;
    float acc[NE];
#pragma unroll
    for (int e = 0; e < NE; e++) acc[e] = 0.f;

    for (int k = lane; k < NF; k += 32) {
        float f = fr[k];
        const float* g = gW + (size_t)k * NE;
#pragma unroll
        for (int e = 0; e < NE; e++) acc[e] = fmaf(f, g[e], acc[e]);
    }
#pragma unroll
    for (int off = 16; off > 0; off >>= 1) {
#pragma unroll
        for (int e = 0; e < NE; e++)
            acc[e] += __shfl_down_sync(0xffffffffu, acc[e], off);
    }
    if (lane == 0) {
        float best0 = -INFINITY, best1 = -INFINITY;
        int i0 = 0, i1 = 0;
#pragma unroll
        for (int e = 0; e < NE; e++) {
            float v = acc[e] + gb[e] + eb[e];
            if (v > best0) { best1 = best0; i1 = i0; best0 = v; i0 = e; }
            else if (v > best1) { best1 = v; i1 = e; }
        }
        // softmax over top-2 (temp = 1)
        float ew = expf(best1 - best0);
        float denom = 1.f + ew;
        float w0 = 1.f / denom;
        float w1 = ew / denom;
        g_topi[2 * t]     = i0;
        g_topi[2 * t + 1] = i1;
        g_topw[2 * t]     = w0;
        g_topw[2 * t + 1] = w1;
        atomicAdd(&g_counts[i0], 1);
        atomicAdd(&g_counts[i1], 1);
    }
}

// -------------------- scatter tokens into expert-grouped slot lists ----------
__global__ void scatter_kernel() {
    int t = blockIdx.x * blockDim.x + threadIdx.x;
    if (t >= NB) return;
#pragma unroll
    for (int j = 0; j < 2; j++) {
        int e = g_topi[2 * t + j];
        int pos = atomicAdd(&g_cursor[e], 1);
        g_rows[pos] = t;
        g_slotof[2 * t + j] = pos;
    }
}

// -------------------- grouped GEMM: 128x128 tile, 8x8/thread, BK=8 -----------
// GATHER=true  : GEMM1 — A rows are feat rows indirected through g_rows,
//                output goes to g_H with ReLU.
// GATHER=false : GEMM2 — A rows are contiguous g_H slots, output to g_Y.
template <int K, int N, bool RELU, bool GATHER>
__global__ __launch_bounds__(256, 2)
void moe_gemm(const float* __restrict__ A_in,   // feat for GEMM1, ignored GEMM2
              const float* __restrict__ Wt,     // [E, K, N]
              const float* __restrict__ bias) { // [E, N]
    const float* A_src = GATHER ? A_in : (const float*)g_H;
    float* Out = RELU ? g_H : g_Y;

    const int e = blockIdx.z;
    const int count = g_counts[e];
    const int m0 = blockIdx.y * 128;
    if (m0 >= count) return;
    const int base = g_offsets[e];
    const int n0 = blockIdx.x * 128;

    __shared__ float As[8][132];
    __shared__ float Bs[8][128];

    const int tid = threadIdx.x;

    // A-tile loader mapping: row ra = tid>>1, 4-float vector va = (tid&1)*4
    const int ra = tid >> 1;
    const int va = (tid & 1) << 2;
    const int ma = m0 + ra;
    const bool valid_a = (ma < count);
    int arow;
    if (GATHER) arow = g_rows[base + (valid_a ? ma : 0)];
    else        arow = base + (valid_a ? ma : 0);
    const float* aptr = A_src + (size_t)arow * K + va;

    // B-tile loader mapping: k-row kb = tid>>5, col vec nb = (tid&31)*4
    const int kb = tid >> 5;
    const int nb = (tid & 31) << 2;
    const float* bptr = Wt + ((size_t)e * K + kb) * N + n0 + nb;

    float acc[8][8];
#pragma unroll
    for (int i = 0; i < 8; i++)
#pragma unroll
        for (int j = 0; j < 8; j++) acc[i][j] = 0.f;

    const int tx = tid & 15;
    const int ty = tid >> 4;

    for (int k0 = 0; k0 < K; k0 += 8) {
        float4 av = valid_a ? *(const float4*)(aptr + k0)
                            : make_float4(0.f, 0.f, 0.f, 0.f);
        float4 bv = *(const float4*)(bptr + (size_t)k0 * N);
        __syncthreads();
        As[va + 0][ra] = av.x;
        As[va + 1][ra] = av.y;
        As[va + 2][ra] = av.z;
        As[va + 3][ra] = av.w;
        *(float4*)&Bs[kb][nb] = bv;
        __syncthreads();
#pragma unroll
        for (int kk = 0; kk < 8; kk++) {
            float a[8], b[8];
            *(float4*)&a[0] = *(const float4*)&As[kk][ty * 8];
            *(float4*)&a[4] = *(const float4*)&As[kk][ty * 8 + 4];
            *(float4*)&b[0] = *(const float4*)&Bs[kk][tx * 8];
            *(float4*)&b[4] = *(const float4*)&Bs[kk][tx * 8 + 4];
#pragma unroll
            for (int i = 0; i < 8; i++)
#pragma unroll
                for (int j = 0; j < 8; j++)
                    acc[i][j] = fmaf(a[i], b[j], acc[i][j]);
        }
    }

    // epilogue: + bias, optional relu, store to Out[slot][n]
    const float* be = bias + (size_t)e * N + n0 + tx * 8;
    float bv8[8];
#pragma unroll
    for (int j = 0; j < 8; j++) bv8[j] = be[j];

#pragma unroll
    for (int i = 0; i < 8; i++) {
        int m = m0 + ty * 8 + i;
        if (m < count) {
            float* orow = Out + (size_t)(base + m) * N + n0 + tx * 8;
            float v[8];
#pragma unroll
            for (int j = 0; j < 8; j++) {
                float x = acc[i][j] + bv8[j];
                v[j] = RELU ? fmaxf(x, 0.f) : x;
            }
            *(float4*)&orow[0] = *(float4*)&v[0];
            *(float4*)&orow[4] = *(float4*)&v[4];
        }
    }
}

// -------------------- combine: out[t] = w0*Y[s0] + w1*Y[s1] ------------------
__global__ void combine_kernel(float* __restrict__ out) {
    int idx = blockIdx.x * blockDim.x + threadIdx.x;  // over NB*NO/4
    int t = idx / (NO / 4);
    int c = (idx % (NO / 4)) * 4;
    if (t >= NB) return;
    float w0 = g_topw[2 * t];
    float w1 = g_topw[2 * t + 1];
    int s0 = g_slotof[2 * t];
    int s1 = g_slotof[2 * t + 1];
    float4 y0 = *(const float4*)&g_Y[(size_t)s0 * NO + c];
    float4 y1 = *(const float4*)&g_Y[(size_t)s1 * NO + c];
    float4 r;
    r.x = w0 * y0.x + w1 * y1.x;
    r.y = w0 * y0.y + w1 * y1.y;
    r.z = w0 * y0.z + w1 * y1.z;
    r.w = w0 * y0.w + w1 * y1.w;
    *(float4*)&out[(size_t)t * NO + c] = r;
}

// -------------------- launch: pure kernel launches only ----------------------
extern "C" void kernel_launch(void* const* d_in, const int* in_sizes, int n_in,
                              void* d_out, int out_size) {
    const float* feat = (const float*)d_in[0];  // [B, F]
    const float* gW   = (const float*)d_in[1];  // [F, E]
    const float* gb   = (const float*)d_in[2];  // [E]
    const float* eb   = (const float*)d_in[3];  // [E]
    const float* W1   = (const float*)d_in[4];  // [E, F, H]
    const float* b1   = (const float*)d_in[5];  // [E, H]
    const float* W2   = (const float*)d_in[6];  // [E, H, O]
    const float* b2   = (const float*)d_in[7];  // [E, O]
    float* out = (float*)d_out;

    init_kernel<<<1, 32>>>();
    router_kernel<<<NB / 8, 256>>>(feat, gW, gb, eb);
    prefix_kernel<<<1, 1>>>();
    scatter_kernel<<<NB / 256, 256>>>();

    // GEMM1: [slots, F] x [F, H] -> g_H (relu), gathered A rows
    {
        dim3 grid(NH / 128, NB / 128, NE);
        moe_gemm<NF, NH, true, true><<<grid, 256>>>(feat, W1, b1);
    }
    // GEMM2: [slots, H] x [H, O] -> g_Y, contiguous A rows
    {
        dim3 grid(NO / 128, NB / 128, NE);
        moe_gemm<NH, NO, false, false><<<grid, 256>>>(nullptr, W2, b2);
    }
    combine_kernel<<<(NB * NO / 4) / 256, 256>>>(out);
}

// round 13
// speedup vs baseline: 2.4236x; 2.4236x over previous
#include <cuda_runtime.h>
#include <cuda_fp16.h>
#include <math.h>
#include <stdint.h>

#define NB 8192      // tokens
#define NF 2048      // feature dim (K of GEMM1)
#define NH 8192      // hidden dim  (N of GEMM1, K of GEMM2)
#define NO 2048      // out dim     (N of GEMM2)
#define NE 8
#define NSLOTS (NB * 2)

// ===================== scratch (device globals, no allocation) ==============
__device__ int   g_counts[NE];
__device__ int   g_offsets[NE];
__device__ int   g_cursor[NE];
__device__ int   g_topi[NB * 2];
__device__ float g_topw[NB * 2];
__device__ int   g_rows[NSLOTS];
__device__ int   g_slotof[NB * 2];

__device__ __align__(256) __half g_Hh[(size_t)NSLOTS * NH];    // hidden fp16
__device__ __align__(256) float  g_Y[(size_t)NSLOTS * NO];

// ===================== mma helper ===========================================
#define MMA16816(d, a, b) \
    asm volatile("mma.sync.aligned.m16n8k16.row.col.f32.f16.f16.f32 " \
        "{%0,%1,%2,%3}, {%4,%5,%6,%7}, {%8,%9}, {%0,%1,%2,%3};" \
        : "+f"((d)[0]), "+f"((d)[1]), "+f"((d)[2]), "+f"((d)[3]) \
        : "r"((a)[0]), "r"((a)[1]), "r"((a)[2]), "r"((a)[3]), \
          "r"((b)[0]), "r"((b)[1]))

// ===================== control kernels ======================================
__global__ void init_kernel() {
    int i = threadIdx.x;
    if (i < NE) g_counts[i] = 0;
}

__global__ void prefix_kernel() {
    int off = 0;
    for (int e = 0; e < NE; e++) {
        g_offsets[e] = off;
        g_cursor[e]  = off;
        off += g_counts[e];
    }
}

__global__ void router_kernel(const float* __restrict__ feat,
                              const float* __restrict__ gW,
                              const float* __restrict__ gb,
                              const float* __restrict__ eb) {
    int warp = threadIdx.x >> 5;
    int lane = threadIdx.x & 31;
    int t = blockIdx.x * 8 + warp;
    if (t >= NB) return;
    const float* fr = feat + (size_t)t * NF;
    float acc[NE];
#pragma unroll
    for (int e = 0; e < NE; e++) acc[e] = 0.f;
    for (int k = lane; k < NF; k += 32) {
        float f = fr[k];
        const float* g = gW + (size_t)k * NE;
#pragma unroll
        for (int e = 0; e < NE; e++) acc[e] = fmaf(f, g[e], acc[e]);
    }
#pragma unroll
    for (int off = 16; off > 0; off >>= 1)
#pragma unroll
        for (int e = 0; e < NE; e++)
            acc[e] += __shfl_down_sync(0xffffffffu, acc[e], off);
    if (lane == 0) {
        float best0 = -INFINITY, best1 = -INFINITY;
        int i0 = 0, i1 = 0;
#pragma unroll
        for (int e = 0; e < NE; e++) {
            float v = acc[e] + gb[e] + eb[e];
            if (v > best0) { best1 = best0; i1 = i0; best0 = v; i0 = e; }
            else if (v > best1) { best1 = v; i1 = e; }
        }
        float ew = expf(best1 - best0);
        float denom = 1.f + ew;
        g_topi[2 * t]     = i0;
        g_topi[2 * t + 1] = i1;
        g_topw[2 * t]     = 1.f / denom;
        g_topw[2 * t + 1] = ew / denom;
        atomicAdd(&g_counts[i0], 1);
        atomicAdd(&g_counts[i1], 1);
    }
}

__global__ void scatter_kernel() {
    int t = blockIdx.x * blockDim.x + threadIdx.x;
    if (t >= NB) return;
#pragma unroll
    for (int j = 0; j < 2; j++) {
        int e = g_topi[2 * t + j];
        int pos = atomicAdd(&g_cursor[e], 1);
        g_rows[pos] = t;
        g_slotof[2 * t + j] = pos;
    }
}

// ===================== HMMA grouped GEMM (no cp.async / no ldmatrix) ========
// CTA tile 128x128, BK=32. A/B tiles in smem as fp16 with 40-half row stride
// (20 words) -> conflict-free fragment gathers via plain LDS.32.
// A: fp32 gathered rows (G1: feat) or fp16 rows (G2: g_Hh), converted inline.
// B: fp32 weights [E][K][N], converted + transposed inline to [n][k].
// 8 warps 2x4, warp tile 64x32, mma.sync.m16n8k16 f32 accum.

#define RS 40   // halves per smem row
#define RSW 20  // words per smem row

template <int K, int NN, bool G1>
__global__ __launch_bounds__(256, 2)
void moe_gemm_hmma(const float* __restrict__ Afeat,  // G1: feat fp32
                   const float* __restrict__ Wt,     // [E][K][NN] fp32
                   const float* __restrict__ bias) { // [E][NN]
    __shared__ __half As[128 * RS];
    __shared__ __half Bs[128 * RS];
    __shared__ int rows_s[128];

    const int e = blockIdx.z;
    const int count = g_counts[e];
    const int m0 = blockIdx.y * 128;
    if (m0 >= count) return;
    const int base = g_offsets[e];
    const int n0 = blockIdx.x * 128;
    const int tid = threadIdx.x;

    if (tid < 128) {
        int m = m0 + tid;
        if (m > count - 1) m = count - 1;
        rows_s[tid] = G1 ? g_rows[base + m] : (base + m);
    }
    __syncthreads();

    // loader indices
    const int ra = tid >> 1;             // A row 0..127
    const int kq = (tid & 1) * 16;       // A k-offset 0/16
    const int kb = tid >> 3;             // B k-row 0..31
    const int nv = (tid & 7) * 16;       // B n-offset

    const float* bp0 = Wt + ((size_t)e * K) * NN + n0 + nv;

    const int w = tid >> 5, lane = tid & 31;
    const int wm = w & 1, wn = w >> 1;   // 2 x 4 warps
    const int lq = lane >> 2, lr = lane & 3;

    float acc[4][4][4];
#pragma unroll
    for (int a = 0; a < 4; a++)
#pragma unroll
        for (int b = 0; b < 4; b++)
#pragma unroll
            for (int c = 0; c < 4; c++) acc[a][b][c] = 0.f;

    const uint32_t* As32 = (const uint32_t*)As;
    const uint32_t* Bs32 = (const uint32_t*)Bs;

    for (int k0 = 0; k0 < K; k0 += 32) {
        // ---- load A tile: 128 rows x 32 k (each thread: 16 halves = 32B) ----
        {
            __half* dst = &As[ra * RS + kq];
            if (G1) {
                const float* ap = Afeat + (size_t)rows_s[ra] * K + k0 + kq;
#pragma unroll
                for (int q = 0; q < 4; q++) {
                    float4 v = ((const float4*)ap)[q];
                    __half2* d2 = (__half2*)(dst + q * 4);
                    d2[0] = __floats2half2_rn(v.x, v.y);
                    d2[1] = __floats2half2_rn(v.z, v.w);
                }
            } else {
                const __half* ap = g_Hh + (size_t)rows_s[ra] * K + k0 + kq;
                uint4 u0 = ((const uint4*)ap)[0];   // 16 B = 8 halves
                uint4 u1 = ((const uint4*)ap)[1];   // 16 B = 8 halves
                ((uint4*)dst)[0] = u0;
                ((uint4*)dst)[1] = u1;
            }
        }
        // ---- load B tile: 32 k-rows x 128 n, transposed to Bs[n][k] ----
        {
            const float* bp = bp0 + (size_t)(k0 + kb) * NN;
#pragma unroll
            for (int q = 0; q < 4; q++) {
                float4 v = ((const float4*)bp)[q];
                int nn = nv + q * 4;
                Bs[(nn + 0) * RS + kb] = __float2half_rn(v.x);
                Bs[(nn + 1) * RS + kb] = __float2half_rn(v.y);
                Bs[(nn + 2) * RS + kb] = __float2half_rn(v.z);
                Bs[(nn + 3) * RS + kb] = __float2half_rn(v.w);
            }
        }
        __syncthreads();

        // ---- compute: 2 k16 steps ----
#pragma unroll
        for (int ks = 0; ks < 2; ks++) {
            const int cc = ks * 8 + lr;
            uint32_t af[4][4], bf[4][2];
#pragma unroll
            for (int mt = 0; mt < 4; mt++) {
                int r0 = wm * 64 + mt * 16 + lq;
                af[mt][0] = As32[r0 * RSW + cc];
                af[mt][1] = As32[(r0 + 8) * RSW + cc];
                af[mt][2] = As32[r0 * RSW + cc + 4];
                af[mt][3] = As32[(r0 + 8) * RSW + cc + 4];
            }
#pragma unroll
            for (int nt = 0; nt < 4; nt++) {
                int nr = wn * 32 + nt * 8 + lq;
                bf[nt][0] = Bs32[nr * RSW + cc];
                bf[nt][1] = Bs32[nr * RSW + cc + 4];
            }
#pragma unroll
            for (int mt = 0; mt < 4; mt++)
#pragma unroll
                for (int nt = 0; nt < 4; nt++)
                    MMA16816(acc[mt][nt], af[mt], bf[nt]);
        }
        __syncthreads();
    }

    // ---- epilogue ----
    const float* bpb = bias + (size_t)e * NN + n0;
#pragma unroll
    for (int mt = 0; mt < 4; mt++) {
#pragma unroll
        for (int hh = 0; hh < 2; hh++) {
            int m = m0 + wm * 64 + mt * 16 + lq + hh * 8;
            if (m < count) {
                size_t orow = (size_t)(base + m) * NN + n0;
#pragma unroll
                for (int nt = 0; nt < 4; nt++) {
                    int col = wn * 32 + nt * 8 + lr * 2;
                    float x0 = acc[mt][nt][hh * 2 + 0] + bpb[col];
                    float x1 = acc[mt][nt][hh * 2 + 1] + bpb[col + 1];
                    if (G1) {
                        x0 = fmaxf(x0, 0.f);
                        x1 = fmaxf(x1, 0.f);
                        *(__half2*)&g_Hh[orow + col] = __floats2half2_rn(x0, x1);
                    } else {
                        *(float2*)&g_Y[orow + col] = make_float2(x0, x1);
                    }
                }
            }
        }
    }
}

// ===================== combine ==============================================
__global__ void combine_kernel(float* __restrict__ out) {
    int idx = blockIdx.x * blockDim.x + threadIdx.x;
    int t = idx / (NO / 4);
    int c = (idx % (NO / 4)) * 4;
    if (t >= NB) return;
    float w0 = g_topw[2 * t];
    float w1 = g_topw[2 * t + 1];
    int s0 = g_slotof[2 * t];
    int s1 = g_slotof[2 * t + 1];
    float4 y0 = *(const float4*)&g_Y[(size_t)s0 * NO + c];
    float4 y1 = *(const float4*)&g_Y[(size_t)s1 * NO + c];
    float4 r;
    r.x = w0 * y0.x + w1 * y1.x;
    r.y = w0 * y0.y + w1 * y1.y;
    r.z = w0 * y0.z + w1 * y1.z;
    r.w = w0 * y0.w + w1 * y1.w;
    *(float4*)&out[(size_t)t * NO + c] = r;
}

// ===================== launch ===============================================
extern "C" void kernel_launch(void* const* d_in, const int* in_sizes, int n_in,
                              void* d_out, int out_size) {
    const float* feat = (const float*)d_in[0];
    const float* gW   = (const float*)d_in[1];
    const float* gb   = (const float*)d_in[2];
    const float* eb   = (const float*)d_in[3];
    const float* W1   = (const float*)d_in[4];  // [E, NF, NH]
    const float* b1   = (const float*)d_in[5];
    const float* W2   = (const float*)d_in[6];  // [E, NH, NO]
    const float* b2   = (const float*)d_in[7];
    float* out = (float*)d_out;

    init_kernel<<<1, 32>>>();
    router_kernel<<<NB / 8, 256>>>(feat, gW, gb, eb);
    prefix_kernel<<<1, 1>>>();
    scatter_kernel<<<NB / 256, 256>>>();

    {
        dim3 grid(NH / 128, NB / 128, NE);
        moe_gemm_hmma<NF, NH, true><<<grid, 256>>>(feat, W1, b1);
    }
    {
        dim3 grid(NO / 128, NB / 128, NE);
        moe_gemm_hmma<NH, NO, false><<<grid, 256>>>(nullptr, W2, b2);
    }
    combine_kernel<<<(NB * NO / 4) / 256, 256>>>(out);
}

// round 14
// speedup vs baseline: 2.6136x; 1.0784x over previous
#include <cuda_runtime.h>
#include <cuda_fp16.h>
#include <math.h>
#include <stdint.h>

#define NB 8192      // tokens
#define NF 2048      // feature dim (K of GEMM1)
#define NH 8192      // hidden dim  (N of GEMM1, K of GEMM2)
#define NO 2048      // out dim     (N of GEMM2)
#define NE 8
#define NSLOTS (NB * 2)

// ===================== scratch (device globals, no allocation) ==============
__device__ int   g_counts[NE];
__device__ int   g_offsets[NE];
__device__ int   g_cursor[NE];
__device__ int   g_topi[NB * 2];
__device__ float g_topw[NB * 2];
__device__ int   g_rows[NSLOTS];
__device__ int   g_slotof[NB * 2];

__device__ __align__(256) __half g_featH[(size_t)NB * NF];     // fp16 features
__device__ __align__(256) __half g_Hh[(size_t)NSLOTS * NH];    // hidden fp16
__device__ __align__(256) float  g_Y[(size_t)NSLOTS * NO];

// ===================== mma helper ===========================================
#define MMA16816(d, a, b) \
    asm volatile("mma.sync.aligned.m16n8k16.row.col.f32.f16.f16.f32 " \
        "{%0,%1,%2,%3}, {%4,%5,%6,%7}, {%8,%9}, {%0,%1,%2,%3};" \
        : "+f"((d)[0]), "+f"((d)[1]), "+f"((d)[2]), "+f"((d)[3]) \
        : "r"((a)[0]), "r"((a)[1]), "r"((a)[2]), "r"((a)[3]), \
          "r"((b)[0]), "r"((b)[1]))

// ===================== control kernels ======================================
__global__ void init_kernel() {
    int i = threadIdx.x;
    if (i < NE) g_counts[i] = 0;
}

__global__ void prefix_kernel() {
    int off = 0;
    for (int e = 0; e < NE; e++) {
        g_offsets[e] = off;
        g_cursor[e]  = off;
        off += g_counts[e];
    }
}

__global__ void router_kernel(const float* __restrict__ feat,
                              const float* __restrict__ gW,
                              const float* __restrict__ gb,
                              const float* __restrict__ eb) {
    int warp = threadIdx.x >> 5;
    int lane = threadIdx.x & 31;
    int t = blockIdx.x * 8 + warp;
    if (t >= NB) return;
    const float* fr = feat + (size_t)t * NF;
    float acc[NE];
#pragma unroll
    for (int e = 0; e < NE; e++) acc[e] = 0.f;
    for (int k = lane; k < NF; k += 32) {
        float f = fr[k];
        const float* g = gW + (size_t)k * NE;
#pragma unroll
        for (int e = 0; e < NE; e++) acc[e] = fmaf(f, g[e], acc[e]);
    }
#pragma unroll
    for (int off = 16; off > 0; off >>= 1)
#pragma unroll
        for (int e = 0; e < NE; e++)
            acc[e] += __shfl_down_sync(0xffffffffu, acc[e], off);
    if (lane == 0) {
        float best0 = -INFINITY, best1 = -INFINITY;
        int i0 = 0, i1 = 0;
#pragma unroll
        for (int e = 0; e < NE; e++) {
            float v = acc[e] + gb[e] + eb[e];
            if (v > best0) { best1 = best0; i1 = i0; best0 = v; i0 = e; }
            else if (v > best1) { best1 = v; i1 = e; }
        }
        float ew = expf(best1 - best0);
        float denom = 1.f + ew;
        g_topi[2 * t]     = i0;
        g_topi[2 * t + 1] = i1;
        g_topw[2 * t]     = 1.f / denom;
        g_topw[2 * t + 1] = ew / denom;
        atomicAdd(&g_counts[i0], 1);
        atomicAdd(&g_counts[i1], 1);
    }
}

__global__ void scatter_kernel() {
    int t = blockIdx.x * blockDim.x + threadIdx.x;
    if (t >= NB) return;
#pragma unroll
    for (int j = 0; j < 2; j++) {
        int e = g_topi[2 * t + j];
        int pos = atomicAdd(&g_cursor[e], 1);
        g_rows[pos] = t;
        g_slotof[2 * t + j] = pos;
    }
}

// ===================== feat -> fp16 pre-pass ================================
__global__ void conv_feat_kernel(const float* __restrict__ f) {
    size_t i = (size_t)blockIdx.x * blockDim.x + threadIdx.x;  // over NB*NF/2
    const float2 v = ((const float2*)f)[i];
    *(__half2*)&g_featH[2 * i] = __floats2half2_rn(v.x, v.y);
}

// ===================== HMMA grouped GEMM (pipelined) ========================
// CTA tile 128x128, BK=32, double-buffered smem with register staging:
//   ldg(next) -> compute(cur, smem) -> sts(next, other buf) -> one sync.
// A: fp16 gathered rows (G1: g_featH via g_rows, G2: g_Hh slots).
// B: fp32 weights [E][K][N], converted + transposed inline to Bs[n][k].
// 8 warps 2x4, warp tile 64x32, mma.sync.m16n8k16 f32 accum. RS=40 pad.

#define RS 40   // halves per smem row
#define RSW 20  // words per smem row

template <int K, int NN, bool G1>
__global__ __launch_bounds__(256, 2)
void moe_gemm_hmma(const float* __restrict__ Wt,     // [E][K][NN] fp32
                   const float* __restrict__ bias) { // [E][NN]
    __shared__ __half As[2][128 * RS];
    __shared__ __half Bs[2][128 * RS];
    __shared__ int rows_s[128];

    const int e = blockIdx.z;
    const int count = g_counts[e];
    const int m0 = blockIdx.y * 128;
    if (m0 >= count) return;
    const int base = g_offsets[e];
    const int n0 = blockIdx.x * 128;
    const int tid = threadIdx.x;

    if (tid < 128) {
        int m = m0 + tid;
        if (m > count - 1) m = count - 1;
        rows_s[tid] = G1 ? g_rows[base + m] : (base + m);
    }
    __syncthreads();

    // loader indices
    const int ra = tid >> 1;             // A row 0..127
    const int kq = (tid & 1) * 16;       // A k-offset 0/16
    const int kb = tid >> 3;             // B k-row 0..31
    const int nv = (tid & 7) * 16;       // B n-offset

    const __half* Ag = G1 ? g_featH : g_Hh;
    const __half* ap0 = Ag + (size_t)rows_s[ra] * K + kq;
    const float*  bp0 = Wt + ((size_t)e * K) * NN + n0 + nv;

    const int w = tid >> 5, lane = tid & 31;
    const int wm = w & 1, wn = w >> 1;   // 2 x 4 warps
    const int lq = lane >> 2, lr = lane & 3;

    float acc[4][4][4];
#pragma unroll
    for (int a = 0; a < 4; a++)
#pragma unroll
        for (int b = 0; b < 4; b++)
#pragma unroll
            for (int c = 0; c < 4; c++) acc[a][b][c] = 0.f;

    // register staging
    uint4  sa0, sa1;                     // A: 16 halves
    float4 sb0, sb1, sb2, sb3;           // B: 16 floats

    auto ldg = [&](int k0) {
        const __half* ap = ap0 + k0;
        sa0 = ((const uint4*)ap)[0];
        sa1 = ((const uint4*)ap)[1];
        const float* bp = bp0 + (size_t)(k0 + kb) * NN;
        sb0 = ((const float4*)bp)[0];
        sb1 = ((const float4*)bp)[1];
        sb2 = ((const float4*)bp)[2];
        sb3 = ((const float4*)bp)[3];
    };
    auto sts = [&](int buf) {
        __half* da = &As[buf][ra * RS + kq];
        ((uint4*)da)[0] = sa0;
        ((uint4*)da)[1] = sa1;
        __half* db = &Bs[buf][0];
        db[(nv + 0)  * RS + kb] = __float2half_rn(sb0.x);
        db[(nv + 1)  * RS + kb] = __float2half_rn(sb0.y);
        db[(nv + 2)  * RS + kb] = __float2half_rn(sb0.z);
        db[(nv + 3)  * RS + kb] = __float2half_rn(sb0.w);
        db[(nv + 4)  * RS + kb] = __float2half_rn(sb1.x);
        db[(nv + 5)  * RS + kb] = __float2half_rn(sb1.y);
        db[(nv + 6)  * RS + kb] = __float2half_rn(sb1.z);
        db[(nv + 7)  * RS + kb] = __float2half_rn(sb1.w);
        db[(nv + 8)  * RS + kb] = __float2half_rn(sb2.x);
        db[(nv + 9)  * RS + kb] = __float2half_rn(sb2.y);
        db[(nv + 10) * RS + kb] = __float2half_rn(sb2.z);
        db[(nv + 11) * RS + kb] = __float2half_rn(sb2.w);
        db[(nv + 12) * RS + kb] = __float2half_rn(sb3.x);
        db[(nv + 13) * RS + kb] = __float2half_rn(sb3.y);
        db[(nv + 14) * RS + kb] = __float2half_rn(sb3.z);
        db[(nv + 15) * RS + kb] = __float2half_rn(sb3.w);
    };

    constexpr int NCH = K / 32;
    ldg(0);
    sts(0);
    __syncthreads();

    for (int i = 0; i < NCH; i++) {
        if (i + 1 < NCH) ldg((i + 1) * 32);

        const uint32_t* As32 = (const uint32_t*)As[i & 1];
        const uint32_t* Bs32 = (const uint32_t*)Bs[i & 1];
#pragma unroll
        for (int ks = 0; ks < 2; ks++) {
            const int cc = ks * 8 + lr;
            uint32_t af[4][4], bf[4][2];
#pragma unroll
            for (int mt = 0; mt < 4; mt++) {
                int r0 = wm * 64 + mt * 16 + lq;
                af[mt][0] = As32[r0 * RSW + cc];
                af[mt][1] = As32[(r0 + 8) * RSW + cc];
                af[mt][2] = As32[r0 * RSW + cc + 4];
                af[mt][3] = As32[(r0 + 8) * RSW + cc + 4];
            }
#pragma unroll
            for (int nt = 0; nt < 4; nt++) {
                int nr = wn * 32 + nt * 8 + lq;
                bf[nt][0] = Bs32[nr * RSW + cc];
                bf[nt][1] = Bs32[nr * RSW + cc + 4];
            }
#pragma unroll
            for (int mt = 0; mt < 4; mt++)
#pragma unroll
                for (int nt = 0; nt < 4; nt++)
                    MMA16816(acc[mt][nt], af[mt], bf[nt]);
        }

        if (i + 1 < NCH) sts((i + 1) & 1);
        __syncthreads();
    }

    // ---- epilogue ----
    const float* bpb = bias + (size_t)e * NN + n0;
#pragma unroll
    for (int mt = 0; mt < 4; mt++) {
#pragma unroll
        for (int hh = 0; hh < 2; hh++) {
            int m = m0 + wm * 64 + mt * 16 + lq + hh * 8;
            if (m < count) {
                size_t orow = (size_t)(base + m) * NN + n0;
#pragma unroll
                for (int nt = 0; nt < 4; nt++) {
                    int col = wn * 32 + nt * 8 + lr * 2;
                    float x0 = acc[mt][nt][hh * 2 + 0] + bpb[col];
                    float x1 = acc[mt][nt][hh * 2 + 1] + bpb[col + 1];
                    if (G1) {
                        x0 = fmaxf(x0, 0.f);
                        x1 = fmaxf(x1, 0.f);
                        *(__half2*)&g_Hh[orow + col] = __floats2half2_rn(x0, x1);
                    } else {
                        *(float2*)&g_Y[orow + col] = make_float2(x0, x1);
                    }
                }
            }
        }
    }
}

// ===================== combine ==============================================
__global__ void combine_kernel(float* __restrict__ out) {
    int idx = blockIdx.x * blockDim.x + threadIdx.x;
    int t = idx / (NO / 4);
    int c = (idx % (NO / 4)) * 4;
    if (t >= NB) return;
    float w0 = g_topw[2 * t];
    float w1 = g_topw[2 * t + 1];
    int s0 = g_slotof[2 * t];
    int s1 = g_slotof[2 * t + 1];
    float4 y0 = *(const float4*)&g_Y[(size_t)s0 * NO + c];
    float4 y1 = *(const float4*)&g_Y[(size_t)s1 * NO + c];
    float4 r;
    r.x = w0 * y0.x + w1 * y1.x;
    r.y = w0 * y0.y + w1 * y1.y;
    r.z = w0 * y0.z + w1 * y1.z;
    r.w = w0 * y0.w + w1 * y1.w;
    *(float4*)&out[(size_t)t * NO + c] = r;
}

// ===================== launch ===============================================
extern "C" void kernel_launch(void* const* d_in, const int* in_sizes, int n_in,
                              void* d_out, int out_size) {
    const float* feat = (const float*)d_in[0];
    const float* gW   = (const float*)d_in[1];
    const float* gb   = (const float*)d_in[2];
    const float* eb   = (const float*)d_in[3];
    const float* W1   = (const float*)d_in[4];  // [E, NF, NH]
    const float* b1   = (const float*)d_in[5];
    const float* W2   = (const float*)d_in[6];  // [E, NH, NO]
    const float* b2   = (const float*)d_in[7];
    float* out = (float*)d_out;

    init_kernel<<<1, 32>>>();
    router_kernel<<<NB / 8, 256>>>(feat, gW, gb, eb);
    prefix_kernel<<<1, 1>>>();
    scatter_kernel<<<NB / 256, 256>>>();
    conv_feat_kernel<<<(NB * NF / 2) / 256, 256>>>(feat);

    {
        dim3 grid(NH / 128, NB / 128, NE);
        moe_gemm_hmma<NF, NH, true><<<grid, 256>>>(W1, b1);
    }
    {
        dim3 grid(NO / 128, NB / 128, NE);
        moe_gemm_hmma<NH, NO, false><<<grid, 256>>>(W2, b2);
    }
    combine_kernel<<<(NB * NO / 4) / 256, 256>>>(out);
}